// round 1
// baseline (speedup 1.0000x reference)
#include <cuda_runtime.h>
#include <math.h>

#define D 512
#define THREADS 128            // 4 elems per thread, float4
#define RATE 0.1f
#define CLIP_MAG 8.0f
#define EPS 1e-4f
#define ACOSH_MIN 1.0001f

__global__ __launch_bounds__(THREADS)
void dropout_hyperbolic_kernel(const float* __restrict__ vecs,
                               const float* __restrict__ curvature,
                               const float* __restrict__ mask_u,
                               float* __restrict__ out)
{
    const int row = blockIdx.x;
    const int tid = threadIdx.x;
    const long base = (long)row * D + tid * 4;

    // One coalesced load pass; keep data in registers.
    float4 v = *reinterpret_cast<const float4*>(vecs + base);
    float4 m = *reinterpret_cast<const float4*>(mask_u + base);

    float k0 = (m.x >= RATE) ? 1.0f : 0.0f;
    float k1 = (m.y >= RATE) ? 1.0f : 0.0f;
    float k2 = (m.z >= RATE) ? 1.0f : 0.0f;
    float k3 = (m.w >= RATE) ? 1.0f : 0.0f;

    // Element 0 of the row is replaced by the hyperboloid projection: it
    // contributes nothing to s, s_keep, or the tangent vector.
    float vx = (tid == 0) ? 0.0f : v.x;

    float s_loc  = vx*vx + v.y*v.y + v.z*v.z + v.w*v.w;
    float sk_loc = vx*vx*k0 + v.y*v.y*k1 + v.z*v.z*k2 + v.w*v.w*k3;

    // Warp reduce (two values).
    #pragma unroll
    for (int off = 16; off > 0; off >>= 1) {
        s_loc  += __shfl_down_sync(0xFFFFFFFFu, s_loc,  off);
        sk_loc += __shfl_down_sync(0xFFFFFFFFu, sk_loc, off);
    }

    __shared__ float sm_s[THREADS / 32];
    __shared__ float sm_k[THREADS / 32];
    const int warp = tid >> 5;
    const int lane = tid & 31;
    if (lane == 0) { sm_s[warp] = s_loc; sm_k[warp] = sk_loc; }
    __syncthreads();

    float s = sm_s[0] + sm_s[1] + sm_s[2] + sm_s[3];
    float sk = sm_k[0] + sm_k[1] + sm_k[2] + sm_k[3];

    // Per-row scalar math (every thread recomputes — cheap).
    const float c = __ldg(curvature);
    const float sqrt_c = sqrtf(c);
    const float inv_keep = 1.0f / (1.0f - RATE);

    float arg = sqrtf(c + s) / sqrt_c - EPS;
    arg = fmaxf(arg, ACOSH_MIN);
    float dist = sqrt_c * acoshf(arg);
    float scale1 = dist / (sqrtf(s) + EPS);

    // ||dropped||^2 = scale1^2 * sk / (1-rate)^2
    float t = scale1 * scale1 * sk * (inv_keep * inv_keep);
    float snv = sqrtf(t) / sqrt_c + EPS;
    float snv_c = fminf(fmaxf(snv, -CLIP_MAG), CLIP_MAG);

    float cosh_v = coshf(snv_c);
    float sinh_v = sinhf(snv_c);

    // out_j = (sinh/snv) * dropped_j = (sinh/snv) * scale1/(1-rate) * v_j*keep_j
    float oscale = (sinh_v / snv) * scale1 * inv_keep;

    float4 r;
    r.x = oscale * v.x * k0;
    r.y = oscale * v.y * k1;
    r.z = oscale * v.z * k2;
    r.w = oscale * v.w * k3;
    if (tid == 0) r.x = cosh_v * sqrt_c;   // out[row][0] = cosh(snv_c)*sqrt(c)

    *reinterpret_cast<float4*>(out + base) = r;
}

extern "C" void kernel_launch(void* const* d_in, const int* in_sizes, int n_in,
                              void* d_out, int out_size)
{
    const float* vecs      = (const float*)d_in[0];
    const float* curvature = (const float*)d_in[1];
    const float* mask_u    = (const float*)d_in[2];
    float* out = (float*)d_out;

    const int n_rows = in_sizes[0] / D;   // 16384
    dropout_hyperbolic_kernel<<<n_rows, THREADS>>>(vecs, curvature, mask_u, out);
}

// round 2
// speedup vs baseline: 1.1367x; 1.1367x over previous
#include <cuda_runtime.h>
#include <math.h>

#define D 512
#define THREADS 128            // 4 elems per thread, float4
#define RATE 0.1f
#define CLIP_MAG 8.0f
#define EPS 1e-4f
#define ACOSH_MIN 1.0001f

__global__ __launch_bounds__(THREADS)
void dropout_hyperbolic_kernel(const float* __restrict__ vecs,
                               const float* __restrict__ curvature,
                               const float* __restrict__ mask_u,
                               float* __restrict__ out)
{
    const int row = blockIdx.x;
    const int tid = threadIdx.x;
    const int base = row * D + tid * 4;

    // One coalesced load pass; keep data in registers.
    float4 v = *reinterpret_cast<const float4*>(vecs + base);
    float4 m = *reinterpret_cast<const float4*>(mask_u + base);

    float k0 = (m.x >= RATE) ? 1.0f : 0.0f;
    float k1 = (m.y >= RATE) ? 1.0f : 0.0f;
    float k2 = (m.z >= RATE) ? 1.0f : 0.0f;
    float k3 = (m.w >= RATE) ? 1.0f : 0.0f;

    // Element 0 of the row is replaced by the hyperboloid projection: it
    // contributes nothing to s, s_keep, or the tangent vector.
    float vx = (tid == 0) ? 0.0f : v.x;

    float s_loc = vx*vx;
    s_loc = fmaf(v.y, v.y, s_loc);
    s_loc = fmaf(v.z, v.z, s_loc);
    s_loc = fmaf(v.w, v.w, s_loc);

    float sk_loc = vx*vx*k0;
    sk_loc = fmaf(v.y*k1, v.y, sk_loc);
    sk_loc = fmaf(v.z*k2, v.z, sk_loc);
    sk_loc = fmaf(v.w*k3, v.w, sk_loc);

    // Warp reduce (two values).
    #pragma unroll
    for (int off = 16; off > 0; off >>= 1) {
        s_loc  += __shfl_down_sync(0xFFFFFFFFu, s_loc,  off);
        sk_loc += __shfl_down_sync(0xFFFFFFFFu, sk_loc, off);
    }

    __shared__ float sm_s[THREADS / 32];
    __shared__ float sm_k[THREADS / 32];
    __shared__ float sm_bcast[2];     // [0]=oscale, [1]=first_val
    const int warp = tid >> 5;
    const int lane = tid & 31;
    if (lane == 0) { sm_s[warp] = s_loc; sm_k[warp] = sk_loc; }
    __syncthreads();

    // One thread does the per-row scalar tail (transcendentals), broadcasts 2 floats.
    if (tid == 0) {
        float s  = sm_s[0] + sm_s[1] + sm_s[2] + sm_s[3];
        float sk = sm_k[0] + sm_k[1] + sm_k[2] + sm_k[3];

        const float c = __ldg(curvature);
        const float sqrt_c = sqrtf(c);
        const float inv_keep = 1.0f / (1.0f - RATE);

        float arg = sqrtf(c + s) / sqrt_c - EPS;
        arg = fmaxf(arg, ACOSH_MIN);
        // acosh(x) = log(x + sqrt(x^2 - 1)); arg >= 1.0001 so this is stable.
        float dist = sqrt_c * __logf(arg + sqrtf(fmaf(arg, arg, -1.0f)));
        float scale1 = dist / (sqrtf(s) + EPS);

        // ||dropped||^2 = scale1^2 * sk / (1-rate)^2
        float t = scale1 * scale1 * sk * (inv_keep * inv_keep);
        float snv = sqrtf(t) / sqrt_c + EPS;
        float snv_c = fminf(fmaxf(snv, -CLIP_MAG), CLIP_MAG);

        // cosh/sinh from a single exp
        float e  = __expf(snv_c);
        float ei = 1.0f / e;
        float cosh_v = 0.5f * (e + ei);
        float sinh_v = 0.5f * (e - ei);

        sm_bcast[0] = (sinh_v / snv) * scale1 * inv_keep;   // oscale
        sm_bcast[1] = cosh_v * sqrt_c;                      // out[row][0]
    }
    __syncthreads();

    const float oscale    = sm_bcast[0];
    const float first_val = sm_bcast[1];

    float4 r;
    r.x = oscale * v.x * k0;
    r.y = oscale * v.y * k1;
    r.z = oscale * v.z * k2;
    r.w = oscale * v.w * k3;
    if (tid == 0) r.x = first_val;

    *reinterpret_cast<float4*>(out + base) = r;
}

extern "C" void kernel_launch(void* const* d_in, const int* in_sizes, int n_in,
                              void* d_out, int out_size)
{
    const float* vecs      = (const float*)d_in[0];
    const float* curvature = (const float*)d_in[1];
    const float* mask_u    = (const float*)d_in[2];
    float* out = (float*)d_out;

    const int n_rows = in_sizes[0] / D;   // 16384
    dropout_hyperbolic_kernel<<<n_rows, THREADS>>>(vecs, curvature, mask_u, out);
}

// round 3
// speedup vs baseline: 1.4480x; 1.2739x over previous
#include <cuda_runtime.h>
#include <math.h>

#define D 512
#define ROWS_PER_BLOCK 8
#define THREADS 256            // 8 warps, 1 row per warp, 16 elems/lane
#define RATE 0.1f
#define CLIP_MAG 8.0f
#define EPS 1e-4f
#define ACOSH_MIN 1.0001f

__global__ __launch_bounds__(THREADS)
void dropout_hyperbolic_kernel(const float* __restrict__ vecs,
                               const float* __restrict__ curvature,
                               const float* __restrict__ mask_u,
                               float* __restrict__ out)
{
    const int warp = threadIdx.x >> 5;
    const int lane = threadIdx.x & 31;
    const int row  = blockIdx.x * ROWS_PER_BLOCK + warp;

    const float4* vp = reinterpret_cast<const float4*>(vecs  + row * D);
    const float4* mp = reinterpret_cast<const float4*>(mask_u + row * D);
    float4*       op = reinterpret_cast<float4*>(out + row * D);

    // Front-batched, fully-coalesced loads: chunk i covers elements
    // [i*128 + lane*4, +4). 8 LDG.128 in flight per thread.
    float4 v[4], m[4];
    #pragma unroll
    for (int i = 0; i < 4; i++) v[i] = vp[lane + i * 32];
    #pragma unroll
    for (int i = 0; i < 4; i++) m[i] = mp[lane + i * 32];

    // kv = v * keep  (keep = mask >= RATE)
    float4 kv[4];
    #pragma unroll
    for (int i = 0; i < 4; i++) {
        kv[i].x = (m[i].x >= RATE) ? v[i].x : 0.0f;
        kv[i].y = (m[i].y >= RATE) ? v[i].y : 0.0f;
        kv[i].z = (m[i].z >= RATE) ? v[i].z : 0.0f;
        kv[i].w = (m[i].w >= RATE) ? v[i].w : 0.0f;
    }

    // Row element 0 (lane 0, chunk 0, .x) is the hyperboloid coordinate:
    // excluded from both sums; its output is overwritten below anyway.
    if (lane == 0) { v[0].x = 0.0f; kv[0].x = 0.0f; }

    // Local partial sums: s = sum v^2, sk = sum (v*keep)^2 = sum kv*v.
    float s_loc = 0.0f, sk_loc = 0.0f;
    #pragma unroll
    for (int i = 0; i < 4; i++) {
        s_loc = fmaf(v[i].x, v[i].x, s_loc);
        s_loc = fmaf(v[i].y, v[i].y, s_loc);
        s_loc = fmaf(v[i].z, v[i].z, s_loc);
        s_loc = fmaf(v[i].w, v[i].w, s_loc);
        sk_loc = fmaf(kv[i].x, v[i].x, sk_loc);
        sk_loc = fmaf(kv[i].y, v[i].y, sk_loc);
        sk_loc = fmaf(kv[i].z, v[i].z, sk_loc);
        sk_loc = fmaf(kv[i].w, v[i].w, sk_loc);
    }

    // Butterfly reduce — all lanes end with the row totals. No barriers.
    #pragma unroll
    for (int off = 16; off > 0; off >>= 1) {
        s_loc  += __shfl_xor_sync(0xFFFFFFFFu, s_loc,  off);
        sk_loc += __shfl_xor_sync(0xFFFFFFFFu, sk_loc, off);
    }

    // Per-row scalar tail, computed redundantly by all 32 lanes (warp-wide
    // issue: same cost as 1 lane, no broadcast needed).
    const float c = __ldg(curvature);
    const float sqrt_c = sqrtf(c);
    const float inv_keep = 1.0f / (1.0f - RATE);

    float arg = sqrtf(c + s_loc) / sqrt_c - EPS;
    arg = fmaxf(arg, ACOSH_MIN);
    // acosh(x) = log(x + sqrt(x^2 - 1)); arg >= 1.0001 so stable.
    float dist = sqrt_c * __logf(arg + sqrtf(fmaf(arg, arg, -1.0f)));
    float scale1 = dist / (sqrtf(s_loc) + EPS);

    float t = scale1 * scale1 * sk_loc * (inv_keep * inv_keep);
    float snv = sqrtf(t) / sqrt_c + EPS;
    float snv_c = fminf(fmaxf(snv, -CLIP_MAG), CLIP_MAG);

    float e  = __expf(snv_c);
    float ei = 1.0f / e;
    float cosh_v = 0.5f * (e + ei);
    float sinh_v = 0.5f * (e - ei);

    const float oscale    = (sinh_v / snv) * scale1 * inv_keep;
    const float first_val = cosh_v * sqrt_c;

    // Output pass (same coalesced layout).
    #pragma unroll
    for (int i = 0; i < 4; i++) {
        float4 r;
        r.x = oscale * kv[i].x;
        r.y = oscale * kv[i].y;
        r.z = oscale * kv[i].z;
        r.w = oscale * kv[i].w;
        if (i == 0 && lane == 0) r.x = first_val;  // out[row][0]
        op[lane + i * 32] = r;
    }
}

extern "C" void kernel_launch(void* const* d_in, const int* in_sizes, int n_in,
                              void* d_out, int out_size)
{
    const float* vecs      = (const float*)d_in[0];
    const float* curvature = (const float*)d_in[1];
    const float* mask_u    = (const float*)d_in[2];
    float* out = (float*)d_out;

    const int n_rows = in_sizes[0] / D;                 // 16384
    const int blocks = n_rows / ROWS_PER_BLOCK;         // 2048
    dropout_hyperbolic_kernel<<<blocks, THREADS>>>(vecs, curvature, mask_u, out);
}

// round 4
// speedup vs baseline: 1.4511x; 1.0021x over previous
#include <cuda_runtime.h>
#include <math.h>

#define D 512
#define ROWS_PER_BLOCK 8
#define THREADS 256            // 8 warps, 1 row per warp, 16 elems/lane
#define RATE 0.1f
#define CLIP_MAG 8.0f
#define EPS 1e-4f
#define ACOSH_MIN 1.0001f

__global__ __launch_bounds__(THREADS, 8)
void dropout_hyperbolic_kernel(const float* __restrict__ vecs,
                               const float* __restrict__ curvature,
                               const float* __restrict__ mask_u,
                               float* __restrict__ out)
{
    const int warp = threadIdx.x >> 5;
    const int lane = threadIdx.x & 31;
    const int row  = blockIdx.x * ROWS_PER_BLOCK + warp;

    const float4* vp = reinterpret_cast<const float4*>(vecs  + row * D);
    const float4* mp = reinterpret_cast<const float4*>(mask_u + row * D);
    float4*       op = reinterpret_cast<float4*>(out + row * D);

    // Front-batched, fully-coalesced loads: chunk i covers elements
    // [i*128 + lane*4, +4). 8 LDG.128 in flight per thread.
    float4 v[4], m[4];
    #pragma unroll
    for (int i = 0; i < 4; i++) v[i] = vp[lane + i * 32];
    #pragma unroll
    for (int i = 0; i < 4; i++) m[i] = mp[lane + i * 32];

    // Row element 0 (lane 0, chunk 0, .x) is the hyperboloid coordinate:
    // excluded from both sums; its output is overwritten below anyway.
    if (lane == 0) v[0].x = 0.0f;

    // Pack keep decisions into a 16-bit mask (bit 4*i+j for chunk i comp j)
    // and accumulate s = sum v^2, sk = sum v^2*keep in the same pass.
    unsigned bits = 0u;
    float s_loc = 0.0f, sk_loc = 0.0f;
    #pragma unroll
    for (int i = 0; i < 4; i++) {
        bool b0 = (m[i].x >= RATE);
        bool b1 = (m[i].y >= RATE);
        bool b2 = (m[i].z >= RATE);
        bool b3 = (m[i].w >= RATE);
        bits |= (unsigned(b0) << (4*i)) | (unsigned(b1) << (4*i+1))
              | (unsigned(b2) << (4*i+2)) | (unsigned(b3) << (4*i+3));
        float x0 = v[i].x * v[i].x;
        float x1 = v[i].y * v[i].y;
        float x2 = v[i].z * v[i].z;
        float x3 = v[i].w * v[i].w;
        s_loc += x0 + x1 + x2 + x3;
        sk_loc += (b0 ? x0 : 0.0f) + (b1 ? x1 : 0.0f)
                + (b2 ? x2 : 0.0f) + (b3 ? x3 : 0.0f);
    }

    // Butterfly reduce — all lanes end with the row totals. No barriers.
    #pragma unroll
    for (int off = 16; off > 0; off >>= 1) {
        s_loc  += __shfl_xor_sync(0xFFFFFFFFu, s_loc,  off);
        sk_loc += __shfl_xor_sync(0xFFFFFFFFu, sk_loc, off);
    }

    // Per-row scalar tail, computed redundantly by all 32 lanes (warp-wide
    // issue: same cost as 1 lane, no broadcast needed).
    const float c = __ldg(curvature);
    const float sqrt_c = sqrtf(c);
    const float inv_keep = 1.0f / (1.0f - RATE);

    float arg = sqrtf(c + s_loc) / sqrt_c - EPS;
    arg = fmaxf(arg, ACOSH_MIN);
    // acosh(x) = log(x + sqrt(x^2 - 1)); arg >= 1.0001 so stable.
    float dist = sqrt_c * __logf(arg + sqrtf(fmaf(arg, arg, -1.0f)));
    float scale1 = dist / (sqrtf(s_loc) + EPS);

    float t = scale1 * scale1 * sk_loc * (inv_keep * inv_keep);
    float snv = sqrtf(t) / sqrt_c + EPS;
    float snv_c = fminf(fmaxf(snv, -CLIP_MAG), CLIP_MAG);

    float e  = __expf(snv_c);
    float ei = 1.0f / e;
    float cosh_v = 0.5f * (e + ei);
    float sinh_v = 0.5f * (e - ei);

    const float oscale    = (sinh_v / snv) * scale1 * inv_keep;
    const float first_val = cosh_v * sqrt_c;

    // Output pass: reconstruct dropped values from the bitmask.
    #pragma unroll
    for (int i = 0; i < 4; i++) {
        float4 r;
        r.x = (bits & (1u << (4*i)))   ? oscale * v[i].x : 0.0f;
        r.y = (bits & (1u << (4*i+1))) ? oscale * v[i].y : 0.0f;
        r.z = (bits & (1u << (4*i+2))) ? oscale * v[i].z : 0.0f;
        r.w = (bits & (1u << (4*i+3))) ? oscale * v[i].w : 0.0f;
        if (i == 0 && lane == 0) r.x = first_val;  // out[row][0]
        op[lane + i * 32] = r;
    }
}

extern "C" void kernel_launch(void* const* d_in, const int* in_sizes, int n_in,
                              void* d_out, int out_size)
{
    const float* vecs      = (const float*)d_in[0];
    const float* curvature = (const float*)d_in[1];
    const float* mask_u    = (const float*)d_in[2];
    float* out = (float*)d_out;

    const int n_rows = in_sizes[0] / D;                 // 16384
    const int blocks = n_rows / ROWS_PER_BLOCK;         // 2048
    dropout_hyperbolic_kernel<<<blocks, THREADS>>>(vecs, curvature, mask_u, out);
}

// round 5
// speedup vs baseline: 1.6675x; 1.1491x over previous
#include <cuda_runtime.h>
#include <math.h>

#define D 512
#define ROWS_PER_BLOCK 8
#define THREADS 256            // 8 warps, 1 row per warp, 16 elems/lane
#define RATE 0.1f
#define CLIP_MAG 8.0f
#define EPS 1e-4f
#define ACOSH_MIN 1.0001f

__global__ __launch_bounds__(THREADS, 8)
void dropout_hyperbolic_kernel(const float* __restrict__ vecs,
                               const float* __restrict__ curvature,
                               const float* __restrict__ mask_u,
                               float* __restrict__ out)
{
    const int warp = threadIdx.x >> 5;
    const int lane = threadIdx.x & 31;
    const int row  = blockIdx.x * ROWS_PER_BLOCK + warp;

    const float4* vp = reinterpret_cast<const float4*>(vecs  + row * D);
    const float4* mp = reinterpret_cast<const float4*>(mask_u + row * D);
    float4*       op = reinterpret_cast<float4*>(out + row * D);

    // Front-batched, fully-coalesced loads: chunk i covers elements
    // [i*128 + lane*4, +4). 8 LDG.128 in flight per thread.
    float4 v[4], m[4];
    #pragma unroll
    for (int i = 0; i < 4; i++) v[i] = vp[lane + i * 32];
    #pragma unroll
    for (int i = 0; i < 4; i++) m[i] = mp[lane + i * 32];

    // Row element 0 (lane 0, chunk 0, .x) is the hyperboloid coordinate:
    // excluded from both sums; its output is overwritten below anyway.
    if (lane == 0) v[0].x = 0.0f;

    // Pack keep decisions into a 16-bit mask (bit 4*i+j for chunk i comp j)
    // and accumulate s = sum v^2, sk = sum v^2*keep in the same pass.
    unsigned bits = 0u;
    float s_loc = 0.0f, sk_loc = 0.0f;
    #pragma unroll
    for (int i = 0; i < 4; i++) {
        bool b0 = (m[i].x >= RATE);
        bool b1 = (m[i].y >= RATE);
        bool b2 = (m[i].z >= RATE);
        bool b3 = (m[i].w >= RATE);
        bits |= (unsigned(b0) << (4*i)) | (unsigned(b1) << (4*i+1))
              | (unsigned(b2) << (4*i+2)) | (unsigned(b3) << (4*i+3));
        float x0 = v[i].x * v[i].x;
        float x1 = v[i].y * v[i].y;
        float x2 = v[i].z * v[i].z;
        float x3 = v[i].w * v[i].w;
        s_loc += x0 + x1 + x2 + x3;
        sk_loc += (b0 ? x0 : 0.0f) + (b1 ? x1 : 0.0f)
                + (b2 ? x2 : 0.0f) + (b3 ? x3 : 0.0f);
    }

    // Butterfly reduce — all lanes end with the row totals. No barriers.
    #pragma unroll
    for (int off = 16; off > 0; off >>= 1) {
        s_loc  += __shfl_xor_sync(0xFFFFFFFFu, s_loc,  off);
        sk_loc += __shfl_xor_sync(0xFFFFFFFFu, sk_loc, off);
    }

    // Per-row scalar tail, computed redundantly by all 32 lanes (warp-wide
    // issue: same cost as 1 lane, no broadcast needed).
    const float c = __ldg(curvature);
    const float sqrt_c = sqrtf(c);
    const float inv_keep = 1.0f / (1.0f - RATE);

    float arg = sqrtf(c + s_loc) / sqrt_c - EPS;
    arg = fmaxf(arg, ACOSH_MIN);
    // acosh(x) = log(x + sqrt(x^2 - 1)); arg >= 1.0001 so stable.
    float dist = sqrt_c * __logf(arg + sqrtf(fmaf(arg, arg, -1.0f)));
    float scale1 = dist / (sqrtf(s_loc) + EPS);

    float t = scale1 * scale1 * sk_loc * (inv_keep * inv_keep);
    float snv = sqrtf(t) / sqrt_c + EPS;
    float snv_c = fminf(fmaxf(snv, -CLIP_MAG), CLIP_MAG);

    float e  = __expf(snv_c);
    float ei = 1.0f / e;
    float cosh_v = 0.5f * (e + ei);
    float sinh_v = 0.5f * (e - ei);

    const float oscale    = (sinh_v / snv) * scale1 * inv_keep;
    const float first_val = cosh_v * sqrt_c;

    // Output pass: reconstruct dropped values from the bitmask.
    // Streaming stores (evict-first): the output is never read, so keep it
    // from evicting the L2-resident inputs between graph replays.
    #pragma unroll
    for (int i = 0; i < 4; i++) {
        float4 r;
        r.x = (bits & (1u << (4*i)))   ? oscale * v[i].x : 0.0f;
        r.y = (bits & (1u << (4*i+1))) ? oscale * v[i].y : 0.0f;
        r.z = (bits & (1u << (4*i+2))) ? oscale * v[i].z : 0.0f;
        r.w = (bits & (1u << (4*i+3))) ? oscale * v[i].w : 0.0f;
        if (i == 0 && lane == 0) r.x = first_val;  // out[row][0]
        __stcs(op + lane + i * 32, r);
    }
}

extern "C" void kernel_launch(void* const* d_in, const int* in_sizes, int n_in,
                              void* d_out, int out_size)
{
    const float* vecs      = (const float*)d_in[0];
    const float* curvature = (const float*)d_in[1];
    const float* mask_u    = (const float*)d_in[2];
    float* out = (float*)d_out;

    const int n_rows = in_sizes[0] / D;                 // 16384
    const int blocks = n_rows / ROWS_PER_BLOCK;         // 2048
    dropout_hyperbolic_kernel<<<blocks, THREADS>>>(vecs, curvature, mask_u, out);
}